// round 3
// baseline (speedup 1.0000x reference)
#include <cuda_runtime.h>

// Fixed problem shape: B=512, Np=128, Ng=128, TIME=5
#define BATCH 512
#define NP 128
#define NG 128
#define TSTEPS 5
#define GI (NG * TSTEPS)     // 640 interpolated gt points
#define NSLICE 4
#define SLICE_PTS (GI / NSLICE)   // 160 points per slice thread
#define CTA_THREADS (NP * NSLICE) // 512

__device__ float        g_partial[BATCH];
__device__ unsigned int g_count = 0;

// ---------- packed f32x2 helpers (sm_103a) ----------
__device__ __forceinline__ unsigned long long pk2(float lo, float hi) {
    unsigned long long r;
    asm("mov.b64 %0, {%1, %2};" : "=l"(r) : "f"(lo), "f"(hi));
    return r;
}
__device__ __forceinline__ void unpk2(unsigned long long v, float& lo, float& hi) {
    asm("mov.b64 {%0, %1}, %2;" : "=f"(lo), "=f"(hi) : "l"(v));
}
__device__ __forceinline__ unsigned long long add2(unsigned long long a, unsigned long long b) {
    unsigned long long r;
    asm("add.rn.f32x2 %0, %1, %2;" : "=l"(r) : "l"(a), "l"(b));
    return r;
}
__device__ __forceinline__ unsigned long long mul2(unsigned long long a, unsigned long long b) {
    unsigned long long r;
    asm("mul.rn.f32x2 %0, %1, %2;" : "=l"(r) : "l"(a), "l"(b));
    return r;
}
__device__ __forceinline__ unsigned long long fma2(unsigned long long a, unsigned long long b,
                                                   unsigned long long c) {
    unsigned long long r;
    asm("fma.rn.f32x2 %0, %1, %2, %3;" : "=l"(r) : "l"(a), "l"(b), "l"(c));
    return r;
}

__device__ __forceinline__ float smooth_l1_elem(float d) {
    d = fabsf(d);
    return (d < 1.0f) ? (0.5f * d * d) : (d - 0.5f);
}

// One CTA per batch. 512 threads: thread (s = tid>>7, p = tid&127) scans
// gt-interp slice [160s, 160s+160) for pred point p.
__global__ void __launch_bounds__(CTA_THREADS) dm_fused(const float2* __restrict__ pred,
                                                        const float2* __restrict__ gt,
                                                        float* __restrict__ out) {
    __shared__ __align__(16) float nxs[GI];   // negated interp x (SoA)
    __shared__ __align__(16) float nys[GI];   // negated interp y
    __shared__ unsigned int s_amin[NSLICE][NP];
    __shared__ float red[NP];
    __shared__ int   s_is_last;

    const int b   = blockIdx.x;
    const int tid = threadIdx.x;
    const int p   = tid & (NP - 1);
    const int sl  = tid >> 7;
    const float2* gtb = gt + b * NG;

    // Build negated interpolation table: interp[n*5+t] = gt[n]*s + gt[n-1]*(1-s)
    for (int i = tid; i < GI; i += CTA_THREADS) {
        int n = i / TSTEPS;
        int t = i - n * TSTEPS;
        float s = (float)t / (float)TSTEPS;
        float2 c  = gtb[n];
        float2 pv = gtb[(n + NG - 1) & (NG - 1)];
        nxs[i] = -(c.x * s + pv.x * (1.0f - s));
        nys[i] = -(c.y * s + pv.y * (1.0f - s));
    }
    __syncthreads();

    const float2 pp = pred[b * NP + p];
    const unsigned long long px2 = pk2(pp.x, pp.x);
    const unsigned long long py2 = pk2(pp.y, pp.y);

    // Branchless argmin over this thread's slice. Embedded key:
    // (float_bits(d) & ~0x3FF) | global_idx  -> umin == first-occurrence argmin.
    const unsigned int MASK = 0xFFFFFC00u;
    unsigned int a0 = 0xFFFFFFFFu, a1 = 0xFFFFFFFFu, a2 = 0xFFFFFFFFu, a3 = 0xFFFFFFFFu;

    const int base0 = sl * SLICE_PTS;
    const ulonglong2* xs2 = reinterpret_cast<const ulonglong2*>(&nxs[base0]);
    const ulonglong2* ys2 = reinterpret_cast<const ulonglong2*>(&nys[base0]);

    #pragma unroll 4
    for (int j = 0; j < SLICE_PTS / 4; ++j) {
        ulonglong2 xv = xs2[j];   // LDS.128: two f32x2 pairs of -interp.x
        ulonglong2 yv = ys2[j];
        unsigned long long dxa = add2(px2, xv.x);
        unsigned long long dxb = add2(px2, xv.y);
        unsigned long long dya = add2(py2, yv.x);
        unsigned long long dyb = add2(py2, yv.y);
        unsigned long long da  = fma2(dya, dya, mul2(dxa, dxa));
        unsigned long long db  = fma2(dyb, dyb, mul2(dxb, dxb));
        float d0, d1, d2, d3;
        unpk2(da, d0, d1);
        unpk2(db, d2, d3);
        unsigned int gidx = (unsigned int)(base0 + 4 * j);
        a0 = min(a0, (__float_as_uint(d0) & MASK) | (gidx + 0u));
        a1 = min(a1, (__float_as_uint(d1) & MASK) | (gidx + 1u));
        a2 = min(a2, (__float_as_uint(d2) & MASK) | (gidx + 2u));
        a3 = min(a3, (__float_as_uint(d3) & MASK) | (gidx + 3u));
    }
    s_amin[sl][p] = min(min(a0, a1), min(a2, a3));
    __syncthreads();

    // Combine the 4 slices per pred point, compute smooth-L1, stage for reduce.
    if (tid < NP) {
        unsigned int best = min(min(s_amin[0][tid], s_amin[1][tid]),
                                min(s_amin[2][tid], s_amin[3][tid]));
        int bi = (int)(best & 0x3FFu);
        float2 q = pred[b * NP + tid];
        float mx = -nxs[bi];
        float my = -nys[bi];
        red[tid] = smooth_l1_elem(q.x - mx) + smooth_l1_elem(q.y - my);
    }
    __syncthreads();

    // Deterministic fixed-order tree over 128 loss values.
    #pragma unroll
    for (int s = 64; s > 0; s >>= 1) {
        if (tid < s) red[tid] += red[tid + s];
        __syncthreads();
    }

    if (tid == 0) {
        g_partial[b] = red[0];
        __threadfence();
        unsigned int old = atomicAdd(&g_count, 1u);
        s_is_last = (old == (unsigned int)(gridDim.x - 1));
    }
    __syncthreads();

    if (s_is_last) {
        __threadfence();
        if (tid < NP) {
            red[tid] = __ldcg(&g_partial[tid])
                     + __ldcg(&g_partial[tid + 128])
                     + __ldcg(&g_partial[tid + 256])
                     + __ldcg(&g_partial[tid + 384]);
        }
        __syncthreads();
        #pragma unroll
        for (int k = 64; k > 0; k >>= 1) {
            if (tid < k) red[tid] += red[tid + k];
            __syncthreads();
        }
        if (tid == 0) {
            out[0] = red[0] * (1.0f / (float)(BATCH * NP * 2));
            g_count = 0;   // reset for next graph replay
        }
    }
}

extern "C" void kernel_launch(void* const* d_in, const int* in_sizes, int n_in,
                              void* d_out, int out_size) {
    const float2* pred = (const float2*)d_in[1];
    const float2* gt   = (const float2*)d_in[2];
    dm_fused<<<BATCH, CTA_THREADS>>>(pred, gt, (float*)d_out);
}

// round 4
// speedup vs baseline: 1.1366x; 1.1366x over previous
#include <cuda_runtime.h>

// Fixed problem shape: B=512, Np=128, Ng=128, TIME=5
#define BATCH 512
#define NP 128
#define NG 128
#define TSTEPS 5
#define GI (NG * TSTEPS)          // 640 interpolated gt points
#define NSLICE 4
#define SLICE_PTS (GI / NSLICE)   // 160 points per slice thread
#define NJ (SLICE_PTS / 4)        // 40 groups of 4 points
#define CTA_THREADS (NP * NSLICE) // 512

__device__ float        g_partial[BATCH];
__device__ unsigned int g_count = 0;

// ---------- packed f32x2 helpers (sm_103a) ----------
__device__ __forceinline__ unsigned long long pk2(float lo, float hi) {
    unsigned long long r;
    asm("mov.b64 %0, {%1, %2};" : "=l"(r) : "f"(lo), "f"(hi));
    return r;
}
__device__ __forceinline__ unsigned long long add2(unsigned long long a, unsigned long long b) {
    unsigned long long r;
    asm("add.rn.f32x2 %0, %1, %2;" : "=l"(r) : "l"(a), "l"(b));
    return r;
}
__device__ __forceinline__ unsigned long long mul2(unsigned long long a, unsigned long long b) {
    unsigned long long r;
    asm("mul.rn.f32x2 %0, %1, %2;" : "=l"(r) : "l"(a), "l"(b));
    return r;
}
__device__ __forceinline__ unsigned long long fma2(unsigned long long a, unsigned long long b,
                                                   unsigned long long c) {
    unsigned long long r;
    asm("fma.rn.f32x2 %0, %1, %2, %3;" : "=l"(r) : "l"(a), "l"(b), "l"(c));
    return r;
}

__device__ __forceinline__ float smooth_l1_elem(float d) {
    d = fabsf(d);
    return (d < 1.0f) ? (0.5f * d * d) : (d - 0.5f);
}

// One CTA per batch. 512 threads: thread (sl = tid>>7, p = tid&127) scans
// gt-interp slice [160*sl, 160*sl+160) for pred point p.
__global__ void __launch_bounds__(CTA_THREADS) dm_fused(const float2* __restrict__ pred,
                                                        const float2* __restrict__ gt,
                                                        float* __restrict__ out) {
    __shared__ __align__(16) float nxs[GI];   // negated interp x (SoA)
    __shared__ __align__(16) float nys[GI];   // negated interp y
    __shared__ unsigned int s_amin[NSLICE][NP];
    __shared__ float s_warp[16];
    __shared__ float red[NP];
    __shared__ int   s_is_last;

    const int b   = blockIdx.x;
    const int tid = threadIdx.x;
    const int p   = tid & (NP - 1);
    const int sl  = tid >> 7;
    const int lane = tid & 31;
    const int wid  = tid >> 5;
    const float2* gtb = gt + b * NG;

    // Build negated interpolation table: interp[n*5+t] = gt[n]*s + gt[n-1]*(1-s)
    for (int i = tid; i < GI; i += CTA_THREADS) {
        int n = i / TSTEPS;
        int t = i - n * TSTEPS;
        float s = (float)t / (float)TSTEPS;
        float2 c  = gtb[n];
        float2 pv = gtb[(n + NG - 1) & (NG - 1)];
        nxs[i] = -(c.x * s + pv.x * (1.0f - s));
        nys[i] = -(c.y * s + pv.y * (1.0f - s));
    }
    __syncthreads();

    const float2 pp = pred[b * NP + p];
    const unsigned long long px2 = pk2(pp.x, pp.x);
    const unsigned long long py2 = pk2(pp.y, pp.y);

    // In-loop key: (dist_bits & 0xFFFFFF00) | j   (j = 4-point group, 0..39,
    // SAME register for all 4 accumulators -> one LOP3 per point, no IADDs).
    // dist >= 0 so bits are uint-monotonic; min == first-occurrence argmin.
    unsigned int a0 = 0xFFFFFFFFu, a1 = 0xFFFFFFFFu, a2 = 0xFFFFFFFFu, a3 = 0xFFFFFFFFu;

    const int base0 = sl * SLICE_PTS;
    const ulonglong2* xs2 = reinterpret_cast<const ulonglong2*>(&nxs[base0]);
    const ulonglong2* ys2 = reinterpret_cast<const ulonglong2*>(&nys[base0]);

    #pragma unroll 8
    for (unsigned int j = 0; j < NJ; ++j) {
        ulonglong2 xv = xs2[j];   // LDS.128: two f32x2 pairs of -interp.x
        ulonglong2 yv = ys2[j];
        unsigned long long dxa = add2(px2, xv.x);
        unsigned long long dxb = add2(px2, xv.y);
        unsigned long long dya = add2(py2, yv.x);
        unsigned long long dyb = add2(py2, yv.y);
        unsigned long long da  = fma2(dya, dya, mul2(dxa, dxa));
        unsigned long long db  = fma2(dyb, dyb, mul2(dxb, dxb));
        // free half-extraction (register-pair selection, no MOV)
        unsigned int d0 = (unsigned int)da;
        unsigned int d1 = (unsigned int)(da >> 32);
        unsigned int d2 = (unsigned int)db;
        unsigned int d3 = (unsigned int)(db >> 32);
        a0 = min(a0, (d0 & 0xFFFFFF00u) | j);
        a1 = min(a1, (d1 & 0xFFFFFF00u) | j);
        a2 = min(a2, (d2 & 0xFFFFFF00u) | j);
        a3 = min(a3, (d3 & 0xFFFFFF00u) | j);
    }
    // Rebuild full local keys: bits[8..31]=quantized dist, bits[0..7]=local idx (j*4+k)
    unsigned int f0 = (a0 & 0xFFFFFF00u) | (((a0 & 0xFFu) << 2) | 0u);
    unsigned int f1 = (a1 & 0xFFFFFF00u) | (((a1 & 0xFFu) << 2) | 1u);
    unsigned int f2 = (a2 & 0xFFFFFF00u) | (((a2 & 0xFFu) << 2) | 2u);
    unsigned int f3 = (a3 & 0xFFFFFF00u) | (((a3 & 0xFFu) << 2) | 3u);
    unsigned int best4 = min(min(f0, f1), min(f2, f3));
    // Global key: bits[10..31]=dist (22 bits), bits[0..9]=global interp idx
    s_amin[sl][p] = (best4 & 0xFFFFFC00u) | (unsigned int)(base0 + (best4 & 0xFFu));
    __syncthreads();

    float wsum = 0.0f;
    if (tid < NP) {
        unsigned int best = min(min(s_amin[0][tid], s_amin[1][tid]),
                                min(s_amin[2][tid], s_amin[3][tid]));
        int bi = (int)(best & 0x3FFu);
        float mx = -nxs[bi];
        float my = -nys[bi];
        float l = smooth_l1_elem(pp.x - mx) + smooth_l1_elem(pp.y - my);
        // deterministic intra-warp reduce (fixed butterfly order)
        #pragma unroll
        for (int o = 16; o > 0; o >>= 1)
            l += __shfl_xor_sync(0xFFFFFFFFu, l, o);
        wsum = l;
    }
    if (tid < NP && lane == 0) s_warp[wid] = wsum;
    __syncthreads();

    if (tid == 0) {
        g_partial[b] = (s_warp[0] + s_warp[1]) + (s_warp[2] + s_warp[3]);
        __threadfence();
        unsigned int old = atomicAdd(&g_count, 1u);
        s_is_last = (old == (unsigned int)(gridDim.x - 1));
    }
    __syncthreads();

    if (s_is_last) {
        __threadfence();
        if (tid < NP) {
            red[tid] = __ldcg(&g_partial[tid])
                     + __ldcg(&g_partial[tid + 128])
                     + __ldcg(&g_partial[tid + 256])
                     + __ldcg(&g_partial[tid + 384]);
        }
        __syncthreads();
        #pragma unroll
        for (int k = 64; k > 0; k >>= 1) {
            if (tid < k) red[tid] += red[tid + k];
            __syncthreads();
        }
        if (tid == 0) {
            out[0] = red[0] * (1.0f / (float)(BATCH * NP * 2));
            g_count = 0;   // reset for next graph replay
        }
    }
}

extern "C" void kernel_launch(void* const* d_in, const int* in_sizes, int n_in,
                              void* d_out, int out_size) {
    const float2* pred = (const float2*)d_in[1];
    const float2* gt   = (const float2*)d_in[2];
    dm_fused<<<BATCH, CTA_THREADS>>>(pred, gt, (float*)d_out);
}